// round 1
// baseline (speedup 1.0000x reference)
#include <cuda_runtime.h>

#define C_DIM 256
#define HW 4096
#define T 8
#define HEADS 8
#define DHEAD 32
#define NWORDS 128            // 4096 / 32
#define CN (C_DIM*HW)         // 1048576
#define TCN (T*CN)            // 8388608
#define EPS 1e-5f

// ---------------- scratch (global, zero-alloc) ----------------
__device__ float    g_xs[TCN];
__device__ float    g_b1[TCN];
__device__ float    g_b2[TCN];
__device__ unsigned g_qmask[T*HEADS*HW];             // 262144 words
__device__ unsigned g_kbits[T*HEADS*DHEAD*NWORDS];   // 262144
__device__ unsigned g_vbits[T*HEADS*DHEAD*NWORDS];   // 262144
__device__ float    g_kv[T*HEADS*DHEAD*DHEAD];       // 65536

// ---------------- LIF over time axis (t = axis 0) ----------------
// v <- (v + x)/2 ; spike = (v >= 1) ; v <- spike ? 0 : v
__global__ void lif_kernel(const float* __restrict__ x, float* __restrict__ s) {
    int i = blockIdx.x*blockDim.x + threadIdx.x;
    if (i >= CN) return;
    float v = 0.f;
#pragma unroll
    for (int t = 0; t < T; t++) {
        v = 0.5f*(v + x[t*CN + i]);
        bool sp = (v >= 1.0f);
        s[t*CN + i] = sp ? 1.0f : 0.0f;
        v = sp ? 0.0f : v;
    }
}

// ---------------- SGEMM with fused BN epilogue ----------------
// Y[b][o][n] = affine( sum_c W[o][c] * X[b][c][n] )
// mode 0: apply BN layer 0.  mode 1: apply BN layer1 then layer2 (composed).
#define BM 128
#define BN_ 128
#define BK 8

__global__ __launch_bounds__(256)
void sgemm_bn(const float* __restrict__ W, const float* __restrict__ X,
              float* __restrict__ Y, const float* __restrict__ bnp, int mode)
{
    __shared__ float As[BK][BM];
    __shared__ float Bs[BK][BN_];

    int b  = blockIdx.z;
    const float* Xb = X + (size_t)b*CN;
    float*       Yb = Y + (size_t)b*CN;
    int m0 = blockIdx.y * BM;
    int n0 = blockIdx.x * BN_;
    int tid = threadIdx.x;
    int tx = tid & 15, ty = tid >> 4;

    int a_m = tid >> 1;           // 0..127
    int a_k = (tid & 1) * 4;      // 0 or 4
    int b_k = tid >> 5;           // 0..7
    int b_n = (tid & 31) * 4;     // 0..124

    float acc[8][8];
#pragma unroll
    for (int i = 0; i < 8; i++)
#pragma unroll
        for (int j = 0; j < 8; j++) acc[i][j] = 0.f;

    for (int kt = 0; kt < 256; kt += BK) {
        float4 av = *(const float4*)&W[(m0 + a_m)*256 + kt + a_k];
        As[a_k+0][a_m] = av.x; As[a_k+1][a_m] = av.y;
        As[a_k+2][a_m] = av.z; As[a_k+3][a_m] = av.w;
        *(float4*)&Bs[b_k][b_n] = *(const float4*)&Xb[(size_t)(kt + b_k)*HW + n0 + b_n];
        __syncthreads();
#pragma unroll
        for (int k = 0; k < BK; k++) {
            float a[8], bb[8];
#pragma unroll
            for (int i = 0; i < 8; i++) a[i]  = As[k][ty*8 + i];
#pragma unroll
            for (int j = 0; j < 8; j++) bb[j] = Bs[k][tx*8 + j];
#pragma unroll
            for (int i = 0; i < 8; i++)
#pragma unroll
                for (int j = 0; j < 8; j++)
                    acc[i][j] = fmaf(a[i], bb[j], acc[i][j]);
        }
        __syncthreads();
    }

#pragma unroll
    for (int i = 0; i < 8; i++) {
        int o = m0 + ty*8 + i;
        float alpha, beta;
        if (mode == 0) {
            float w = bnp[0*1024 + 0*256 + o], bb2 = bnp[0*1024 + 1*256 + o];
            float m = bnp[0*1024 + 2*256 + o], v   = bnp[0*1024 + 3*256 + o];
            alpha = w * rsqrtf(v + EPS);
            beta  = bb2 - alpha * m;
        } else {
            float w1 = bnp[1*1024 + 0*256 + o], b1 = bnp[1*1024 + 1*256 + o];
            float m1 = bnp[1*1024 + 2*256 + o], v1 = bnp[1*1024 + 3*256 + o];
            float w2 = bnp[2*1024 + 0*256 + o], b2 = bnp[2*1024 + 1*256 + o];
            float m2 = bnp[2*1024 + 2*256 + o], v2 = bnp[2*1024 + 3*256 + o];
            float a1 = w1 * rsqrtf(v1 + EPS), c1 = b1 - a1*m1;
            float a2 = w2 * rsqrtf(v2 + EPS), c2 = b2 - a2*m2;
            alpha = a1*a2;
            beta  = a2*c1 + c2;
        }
        float* yrow = Yb + (size_t)o*HW + n0 + tx*8;
#pragma unroll
        for (int j = 0; j < 8; j++) yrow[j] = fmaf(alpha, acc[i][j], beta);
    }
}

// ---------------- depthwise 3x3, border = BN-layer0 affine(0) ----------------
__global__ __launch_bounds__(256)
void dwconv(const float* __restrict__ Yin, const float* __restrict__ dwW,
            const float* __restrict__ bnp, float* __restrict__ Z)
{
    __shared__ float tile[4096];
    int c = blockIdx.x;
    int b = blockIdx.y;
    const float* in  = Yin + ((size_t)b*C_DIM + c)*HW;
    float*       out = Z   + ((size_t)b*C_DIM + c)*HW;
    int tid = threadIdx.x;
    for (int p = tid; p < 4096; p += 256) tile[p] = in[p];

    float wgt[9];
#pragma unroll
    for (int i = 0; i < 9; i++) wgt[i] = dwW[c*9 + i];
    float w0 = bnp[0*256 + c], bb = bnp[1*256 + c];
    float mm = bnp[2*256 + c], vv = bnp[3*256 + c];
    float alpha = w0 * rsqrtf(vv + EPS);
    float pad = bb - alpha * mm;
    __syncthreads();

    for (int p = tid; p < 4096; p += 256) {
        int h = p >> 6, w = p & 63;
        float s = 0.f;
#pragma unroll
        for (int dy = -1; dy <= 1; dy++)
#pragma unroll
            for (int dx = -1; dx <= 1; dx++) {
                int hh = h + dy, ww = w + dx;
                float val = (hh >= 0 && hh < 64 && ww >= 0 && ww < 64)
                            ? tile[hh*64 + ww] : pad;
                s = fmaf(wgt[(dy+1)*3 + (dx+1)], val, s);
            }
        out[p] = s;
    }
}

// ---------------- fused LIF + bitpack over n (k and v) ----------------
// bits[(t*8+h)*32+dd][grp] = ballot of spikes at n = grp*32 + lane
__global__ void lif_pack(const float* __restrict__ g, unsigned* __restrict__ bits) {
    int gw   = (blockIdx.x*blockDim.x + threadIdx.x) >> 5;
    int lane = threadIdx.x & 31;
    if (gw >= C_DIM*NWORDS) return;
    int c = gw >> 7, grp = gw & 127;
    int n = grp*32 + lane;
    int h = c >> 5, dd = c & 31;
    float v = 0.f;
#pragma unroll
    for (int t = 0; t < T; t++) {
        v = 0.5f*(v + g[((size_t)t*C_DIM + c)*HW + n]);
        bool sp = (v >= 1.0f);
        unsigned m = __ballot_sync(0xffffffffu, sp);
        v = sp ? 0.f : v;
        if (lane == 0) bits[(((size_t)t*HEADS + h)*DHEAD + dd)*NWORDS + grp] = m;
    }
}

// ---------------- pack q spikes over channel-within-head ----------------
__global__ void qpack(const float* __restrict__ qs, unsigned* __restrict__ qm) {
    int i = blockIdx.x*blockDim.x + threadIdx.x;  // (t*8+h)*4096 + n
    if (i >= T*HEADS*HW) return;
    int n  = i & (HW-1);
    int th = i >> 12;
    int t = th >> 3, h = th & 7;
    const float* base = qs + ((size_t)t*C_DIM + h*DHEAD)*HW + n;
    unsigned word = 0;
#pragma unroll
    for (int dd = 0; dd < 32; dd++)
        word |= (base[(size_t)dd*HW] != 0.f ? 1u : 0u) << dd;
    qm[i] = word;
}

// ---------------- kv = k^T v  (exact, popcount) ----------------
__global__ __launch_bounds__(1024)
void kv_kernel(const unsigned* __restrict__ kb, const unsigned* __restrict__ vb,
               float* __restrict__ kv)
{
    __shared__ unsigned sk[DHEAD][NWORDS+1];
    __shared__ unsigned sv[DHEAD][NWORDS+1];
    int bh = blockIdx.x;
    const unsigned* kbase = kb + (size_t)bh*DHEAD*NWORDS;
    const unsigned* vbase = vb + (size_t)bh*DHEAD*NWORDS;
    int tid = threadIdx.x;
    for (int i = tid; i < DHEAD*NWORDS; i += 1024) {
        sk[i >> 7][i & 127] = kbase[i];
        sv[i >> 7][i & 127] = vbase[i];
    }
    __syncthreads();
    int dd = tid >> 5, e = tid & 31;
    int cnt = 0;
#pragma unroll 8
    for (int w = 0; w < NWORDS; w++)
        cnt += __popc(sk[dd][w] & sv[e][w]);
    kv[(size_t)bh*1024 + dd*32 + e] = (float)cnt;
}

// ---------------- o = q @ kv * scale, fused LIF over t ----------------
__global__ __launch_bounds__(128)
void o_lif(const unsigned* __restrict__ qm, const float* __restrict__ kv,
           float* __restrict__ os)
{
    __shared__ float skv[DHEAD*DHEAD];
    int h = blockIdx.y;
    int n = blockIdx.x*128 + threadIdx.x;
    const float scale = 0.17677669529663687f;   // 32^-0.5
    float vst[32];
#pragma unroll
    for (int e = 0; e < 32; e++) vst[e] = 0.f;

    for (int t = 0; t < T; t++) {
        __syncthreads();
        for (int i = threadIdx.x; i < 1024; i += 128)
            skv[i] = kv[((size_t)t*HEADS + h)*1024 + i];
        __syncthreads();
        unsigned q = qm[((size_t)t*HEADS + h)*HW + n];
        float acc[32];
#pragma unroll
        for (int e = 0; e < 32; e++) acc[e] = 0.f;
#pragma unroll
        for (int dd = 0; dd < 32; dd++) {
            float bit = (float)((q >> dd) & 1u);
#pragma unroll
            for (int e = 0; e < 32; e++)
                acc[e] = fmaf(bit, skv[dd*32 + e], acc[e]);
        }
#pragma unroll
        for (int e = 0; e < 32; e++) {
            float ov = acc[e]*scale;
            float vv = 0.5f*(vst[e] + ov);
            bool sp = (vv >= 1.0f);
            os[((size_t)t*C_DIM + h*DHEAD + e)*HW + n] = sp ? 1.0f : 0.0f;
            vst[e] = sp ? 0.f : vv;
        }
    }
}

// ---------------- launch ----------------
extern "C" void kernel_launch(void* const* d_in, const int* in_sizes, int n_in,
                              void* d_out, int out_size)
{
    const float* x = (const float*)d_in[0];
    const float* w1[4] = {(const float*)d_in[1], (const float*)d_in[5],
                          (const float*)d_in[9], (const float*)d_in[13]};
    const float* dw[4] = {(const float*)d_in[2], (const float*)d_in[6],
                          (const float*)d_in[10], (const float*)d_in[14]};
    const float* pw[4] = {(const float*)d_in[3], (const float*)d_in[7],
                          (const float*)d_in[11], (const float*)d_in[15]};
    const float* bn[4] = {(const float*)d_in[4], (const float*)d_in[8],
                          (const float*)d_in[12], (const float*)d_in[16]};

    float *xs, *b1, *b2, *kvp;
    unsigned *qm, *kb, *vb;
    cudaGetSymbolAddress((void**)&xs, g_xs);
    cudaGetSymbolAddress((void**)&b1, g_b1);
    cudaGetSymbolAddress((void**)&b2, g_b2);
    cudaGetSymbolAddress((void**)&qm, g_qmask);
    cudaGetSymbolAddress((void**)&kb, g_kbits);
    cudaGetSymbolAddress((void**)&vb, g_vbits);
    cudaGetSymbolAddress((void**)&kvp, g_kv);

    dim3 gemm_grid(HW/BN_, C_DIM/BM, T);   // (32, 2, 8)
    dim3 dw_grid(C_DIM, T);                // (256, 8)

    // input LIF
    lif_kernel<<<CN/256, 256>>>(x, xs);

    // q branch
    sgemm_bn<<<gemm_grid, 256>>>(w1[0], xs, b1, bn[0], 0);
    dwconv  <<<dw_grid,   256>>>(b1, dw[0], bn[0], b2);
    sgemm_bn<<<gemm_grid, 256>>>(pw[0], b2, b1, bn[0], 1);
    lif_kernel<<<CN/256, 256>>>(b1, b2);
    qpack<<<(T*HEADS*HW)/256, 256>>>(b2, qm);

    // k branch
    sgemm_bn<<<gemm_grid, 256>>>(w1[1], xs, b1, bn[1], 0);
    dwconv  <<<dw_grid,   256>>>(b1, dw[1], bn[1], b2);
    sgemm_bn<<<gemm_grid, 256>>>(pw[1], b2, b1, bn[1], 1);
    lif_pack<<<(C_DIM*NWORDS*32)/256, 256>>>(b1, kb);

    // v branch
    sgemm_bn<<<gemm_grid, 256>>>(w1[2], xs, b1, bn[2], 0);
    dwconv  <<<dw_grid,   256>>>(b1, dw[2], bn[2], b2);
    sgemm_bn<<<gemm_grid, 256>>>(pw[2], b2, b1, bn[2], 1);
    lif_pack<<<(C_DIM*NWORDS*32)/256, 256>>>(b1, vb);

    // attention (exact integer via popcount) + LIF -> spike tensor in b1
    kv_kernel<<<T*HEADS, 1024>>>(kb, vb, kvp);
    o_lif<<<dim3(HW/128, HEADS), 128>>>(qm, kvp, b1);

    // projection branch -> d_out
    sgemm_bn<<<gemm_grid, 256>>>(w1[3], b1, b2, bn[3], 0);
    dwconv  <<<dw_grid,   256>>>(b2, dw[3], bn[3], b1);
    sgemm_bn<<<gemm_grid, 256>>>(pw[3], b1, (float*)d_out, bn[3], 1);
}